// round 15
// baseline (speedup 1.0000x reference)
#include <cuda_runtime.h>
#include <cuda_bf16.h>
#include <math.h>
#include <stdint.h>

#define B_    2
#define S_    2048
#define DIN   1024
#define DOUT  1024
#define NH    16
#define HD_   64
#define WIN   256
#define SCALE 0.125f

#define NQKV (B_*NH*S_*HD_)
#define NX   (B_*S_*DIN)

__device__ __align__(16) __nv_bfloat16 gx_h[NX],  gx_l[NX];
__device__ __align__(16) __nv_bfloat16 gwq_h[3*DOUT*DIN], gwq_l[3*DOUT*DIN];
__device__ __align__(16) __nv_bfloat16 gwo_h[DOUT*DOUT],  gwo_l[DOUT*DOUT];
__device__ __align__(16) __nv_bfloat16 gq_h[NQKV], gq_l[NQKV];
__device__ __align__(16) __nv_bfloat16 gk_h[NQKV], gk_l[NQKV];
__device__ __align__(16) __nv_bfloat16 gv_h[NQKV], gv_l[NQKV];
__device__ __align__(16) __nv_bfloat16 gc_h[B_*S_*DOUT], gc_l[B_*S_*DOUT];

// ===========================================================================
__device__ __forceinline__ void split2(float x, float y, uint32_t& hi, uint32_t& lo) {
    __nv_bfloat16 hx = __float2bfloat16(x);
    __nv_bfloat16 hy = __float2bfloat16(y);
    float rx = x - __bfloat162float(hx);
    float ry = y - __bfloat162float(hy);
    __nv_bfloat16 lx = __float2bfloat16(rx);
    __nv_bfloat16 ly = __float2bfloat16(ry);
    __nv_bfloat162 hv; hv.x = hx; hv.y = hy;
    __nv_bfloat162 lv; lv.x = lx; lv.y = ly;
    hi = *(uint32_t*)&hv;
    lo = *(uint32_t*)&lv;
}

__device__ __forceinline__ void mma_bf16(float c[4], const uint32_t a[4], const uint32_t b[2]) {
    asm volatile(
        "mma.sync.aligned.m16n8k16.row.col.f32.bf16.bf16.f32 "
        "{%0,%1,%2,%3}, {%4,%5,%6,%7}, {%8,%9}, {%0,%1,%2,%3};"
        : "+f"(c[0]), "+f"(c[1]), "+f"(c[2]), "+f"(c[3])
        : "r"(a[0]), "r"(a[1]), "r"(a[2]), "r"(a[3]), "r"(b[0]), "r"(b[1]));
}

#define CPA16(dst, src) asm volatile("cp.async.cg.shared.global [%0], [%1], 16;" :: "r"(dst), "l"(src))
#define CPC()  asm volatile("cp.async.commit_group;" ::: "memory")
#define CPW(n) asm volatile("cp.async.wait_group %0;" :: "n"(n) : "memory")

#define LDSM4(d0,d1,d2,d3,a) \
    asm volatile("ldmatrix.sync.aligned.m8n8.x4.shared.b16 {%0,%1,%2,%3}, [%4];" \
                 : "=r"(d0),"=r"(d1),"=r"(d2),"=r"(d3) : "r"(a))
#define LDSM4T(d0,d1,d2,d3,a) \
    asm volatile("ldmatrix.sync.aligned.m8n8.x4.trans.shared.b16 {%0,%1,%2,%3}, [%4];" \
                 : "=r"(d0),"=r"(d1),"=r"(d2),"=r"(d3) : "r"(a))

__device__ __forceinline__ uint32_t scvta(const void* p) {
    return (uint32_t)__cvta_generic_to_shared(p);
}

// ===========================================================================
// Fused split: one launch covers x, W_qkv, W_out (fp32 -> bf16 hi/lo).
// ===========================================================================
#define N4_X   (NX / 4)
#define N4_WQ  (3 * DOUT * DIN / 4)
#define N4_WO  (DOUT * DOUT / 4)
#define N4_ALL (N4_X + N4_WQ + N4_WO)

__global__ void split_all_kernel(const float4* __restrict__ x,
                                 const float4* __restrict__ wq,
                                 const float4* __restrict__ wo)
{
    int i = blockIdx.x * 256 + threadIdx.x;
    const float4* src;
    uint2 *hi, *lo;
    int j;
    if (i < N4_X) {
        src = x;  j = i;
        hi = (uint2*)gx_h;  lo = (uint2*)gx_l;
    } else if (i < N4_X + N4_WQ) {
        src = wq; j = i - N4_X;
        hi = (uint2*)gwq_h; lo = (uint2*)gwq_l;
    } else {
        src = wo; j = i - N4_X - N4_WQ;
        hi = (uint2*)gwo_h; lo = (uint2*)gwo_l;
    }
    float4 v = src[j];
    uint32_t h0, l0, h1, l1;
    split2(v.x, v.y, h0, l0);
    split2(v.z, v.w, h1, l1);
    hi[j] = make_uint2(h0, h1);
    lo[j] = make_uint2(l0, l1);
}

// ===========================================================================
// GEMM: C[128x256]/CTA, 8 warps, 64x64 warp tile, BK=64, 2-stage cp.async,
// bf16 3-pass. NEW: ah/bh fragments for kc+1 preloaded (into the SAME
// registers, whose lifetimes have ended) during kc's pass-3 MMA stream, so
// only kc=0 has a serial LDSM prefix. MMA order identical to R11.
// ===========================================================================
#define PRB       144
#define GA_B      (128 * PRB)
#define GB_B      (256 * PRB)
#define GSTAGE_B  (2 * GA_B + 2 * GB_B)
#define GOFF_AL   GA_B
#define GOFF_BH   (2 * GA_B)
#define GOFF_BL   (GOFF_BH + GB_B)
#define GEMM_SMEM (2 * GSTAGE_B)

__device__ __forceinline__ void gstage(const __nv_bfloat16* Ah, const __nv_bfloat16* Al,
                                       const __nv_bfloat16* Bh, const __nv_bfloat16* Bl,
                                       int k0, uint32_t sb, int t)
{
#pragma unroll
    for (int it = 0; it < 4; it++) {
        int idx = t + it * 256;
        int row = idx >> 3, c = idx & 7;
        uint32_t d = sb + row * PRB + c * 16;
        CPA16(d,           Ah + (size_t)row * 1024 + k0 + c * 8);
        CPA16(d + GOFF_AL, Al + (size_t)row * 1024 + k0 + c * 8);
    }
#pragma unroll
    for (int it = 0; it < 8; it++) {
        int idx = t + it * 256;
        int row = idx >> 3, c = idx & 7;
        uint32_t d = sb + GOFF_BH + row * PRB + c * 16;
        CPA16(d,        Bh + (size_t)row * 1024 + k0 + c * 8);
        CPA16(d + GB_B, Bl + (size_t)row * 1024 + k0 + c * 8);
    }
}

__device__ __forceinline__ void docp(int j,
                                     const __nv_bfloat16* Ah, const __nv_bfloat16* Al,
                                     const __nv_bfloat16* Bh, const __nv_bfloat16* Bl,
                                     int k0, uint32_t sb, int t)
{
    if (j < 8) {
        int it = j & 3;
        int idx = t + it * 256;
        int row = idx >> 3, c = idx & 7;
        uint32_t d = sb + row * PRB + c * 16;
        if (j < 4) CPA16(d,           Ah + (size_t)row * 1024 + k0 + c * 8);
        else       CPA16(d + GOFF_AL, Al + (size_t)row * 1024 + k0 + c * 8);
    } else {
        int jj = j - 8;
        int it = jj & 7;
        int idx = t + it * 256;
        int row = idx >> 3, c = idx & 7;
        uint32_t d = sb + GOFF_BH + row * PRB + c * 16;
        if (jj < 8) CPA16(d,        Bh + (size_t)row * 1024 + k0 + c * 8);
        else        CPA16(d + GB_B, Bl + (size_t)row * 1024 + k0 + c * 8);
    }
}

__device__ __forceinline__ void mma_g8(float (*accr)[4], const uint32_t a[4],
                                       const uint32_t (*b)[2])
{
#pragma unroll
    for (int j = 0; j < 8; j++) mma_bf16(accr[j], a, b[j]);
}

__device__ __forceinline__ void gemm_main(const __nv_bfloat16* Ah, const __nv_bfloat16* Al,
                                          const __nv_bfloat16* Bh, const __nv_bfloat16* Bl,
                                          uint32_t sb, float acc[4][8][4])
{
    const int t = threadIdx.x;
    const int lane = t & 31, wid = t >> 5;
    const int wm = wid >> 2, wn = wid & 3;

    // fragment addresses (kc enters as byte offset kc*32)
    const int rB = wn * 64 + (lane >> 4) * 8 + (lane & 7);   // +jp*16
    const int rA = wm * 64 + (lane & 15);                    // +i*16
    const uint32_t offB = ((lane >> 3) & 1) * 16;
    const uint32_t offA = (lane >> 4) * 16;

#pragma unroll
    for (int i = 0; i < 4; i++)
#pragma unroll
        for (int j = 0; j < 8; j++)
#pragma unroll
            for (int c = 0; c < 4; c++) acc[i][j][c] = 0.f;

    gstage(Ah, Al, Bh, Bl, 0, sb, t);
    CPC();

    for (int ks = 0; ks < 16; ks++) {
        CPW(0);
        __syncthreads();
        const uint32_t cs = sb + (ks & 1) * GSTAGE_B;
        const uint32_t ps = sb + ((ks + 1) & 1) * GSTAGE_B;
        const int k0n = (ks + 1) * 64;
        const bool pf = (ks < 15);

        uint32_t ah[4][4], bh[8][2];
        // prefix only for kc=0
#pragma unroll
        for (int jp = 0; jp < 4; jp++) {
            uint32_t a = cs + GOFF_BH + (rB + jp * 16) * PRB + offB;
            LDSM4(bh[2*jp][0], bh[2*jp][1], bh[2*jp+1][0], bh[2*jp+1][1], a);
        }
#pragma unroll
        for (int i = 0; i < 4; i++) {
            LDSM4(ah[i][0], ah[i][1], ah[i][2], ah[i][3],
                  cs + (rA + i * 16) * PRB + offA);
        }

#pragma unroll
        for (int kc = 0; kc < 4; kc++) {
            uint32_t al[4][4], bl[8][2];
            // pass 1: Ah*Bh, A-lo LDSM + cp interleaved
#pragma unroll
            for (int i = 0; i < 4; i++) {
                mma_g8(acc[i], ah[i], bh);
                LDSM4(al[i][0], al[i][1], al[i][2], al[i][3],
                      cs + GOFF_AL + (rA + i * 16) * PRB + kc * 32 + offA);
                int gi = kc * 12 + i;
                if (pf && gi < 24) docp(gi, Ah, Al, Bh, Bl, k0n, ps, t);
            }
            // pass 2: Al*Bh, B-lo LDSM + cp interleaved
#pragma unroll
            for (int i = 0; i < 4; i++) {
                mma_g8(acc[i], al[i], bh);
                uint32_t a = cs + GOFF_BL + (rB + i * 16) * PRB + kc * 32 + offB;
                LDSM4(bl[2*i][0], bl[2*i][1], bl[2*i+1][0], bl[2*i+1][1], a);
                int gi = kc * 12 + 4 + i;
                if (pf && gi < 24) docp(gi, Ah, Al, Bh, Bl, k0n, ps, t);
            }
            // pass 3: Ah*Bl; preload kc+1's bh/ah into the now-dead registers
#pragma unroll
            for (int i = 0; i < 4; i++) {
                mma_g8(acc[i], ah[i], bl);           // last use of ah[i]
                if (kc < 3) {
                    uint32_t a = cs + GOFF_BH + (rB + i * 16) * PRB + (kc + 1) * 32 + offB;
                    LDSM4(bh[2*i][0], bh[2*i][1], bh[2*i+1][0], bh[2*i+1][1], a);
                    LDSM4(ah[i][0], ah[i][1], ah[i][2], ah[i][3],
                          cs + (rA + i * 16) * PRB + (kc + 1) * 32 + offA);
                }
                int gi = kc * 12 + 8 + i;
                if (pf && gi < 24) docp(gi, Ah, Al, Bh, Bl, k0n, ps, t);
            }
        }
        CPC();
    }
}

__global__ __launch_bounds__(256, 1) void qkv_gemm_k()
{
    extern __shared__ char smg[];
    uint32_t sb = scvta(smg);
    const int m0 = blockIdx.y * 128;
    const int n0 = blockIdx.x * 256;

    float acc[4][8][4];
    gemm_main(gx_h + (size_t)m0 * 1024, gx_l + (size_t)m0 * 1024,
              gwq_h + (size_t)n0 * 1024, gwq_l + (size_t)n0 * 1024, sb, acc);

    const int t = threadIdx.x;
    const int lane = t & 31, wid = t >> 5;
    const int wm = wid >> 2, wn = wid & 3;
    const int g = lane >> 2, tq = lane & 3;

    const int which = n0 >> 10;
    __nv_bfloat16* dh = (which == 0) ? gq_h : (which == 1) ? gk_h : gv_h;
    __nv_bfloat16* dl = (which == 0) ? gq_l : (which == 1) ? gk_l : gv_l;
    const int h = ((n0 + wn * 64) >> 6) & (NH - 1);

#pragma unroll
    for (int i = 0; i < 4; i++) {
        int m = m0 + wm * 64 + i * 16 + g;
        int b = m >> 11, s = m & (S_ - 1);
#pragma unroll
        for (int j = 0; j < 8; j++) {
            int hd = j * 8 + 2 * tq;
            size_t idx = (((size_t)(b * NH + h) * S_ + s) * HD_ + hd);
            uint32_t hw, lw;
            split2(acc[i][j][0], acc[i][j][1], hw, lw);
            *(uint32_t*)(dh + idx) = hw;
            *(uint32_t*)(dl + idx) = lw;
            split2(acc[i][j][2], acc[i][j][3], hw, lw);
            *(uint32_t*)(dh + idx + 8 * HD_) = hw;
            *(uint32_t*)(dl + idx + 8 * HD_) = lw;
        }
    }
}

__global__ __launch_bounds__(256, 1) void out_gemm_k(const float* __restrict__ bias,
                                                     float* __restrict__ out)
{
    extern __shared__ char smg[];
    uint32_t sb = scvta(smg);
    const int m0 = blockIdx.y * 128;
    const int n0 = blockIdx.x * 256;

    float acc[4][8][4];
    gemm_main(gc_h + (size_t)m0 * 1024, gc_l + (size_t)m0 * 1024,
              gwo_h + (size_t)n0 * 1024, gwo_l + (size_t)n0 * 1024, sb, acc);

    const int t = threadIdx.x;
    const int lane = t & 31, wid = t >> 5;
    const int wm = wid >> 2, wn = wid & 3;
    const int g = lane >> 2, tq = lane & 3;

#pragma unroll
    for (int i = 0; i < 4; i++) {
        int m = m0 + wm * 64 + i * 16 + g;
#pragma unroll
        for (int j = 0; j < 8; j++) {
            int nn = n0 + wn * 64 + j * 8 + 2 * tq;
            float2 bb = *(const float2*)(bias + nn);
            float* p = out + (size_t)m * DOUT + nn;
            *(float2*)p              = make_float2(acc[i][j][0] + bb.x, acc[i][j][1] + bb.y);
            *(float2*)(p + 8 * DOUT) = make_float2(acc[i][j][2] + bb.x, acc[i][j][3] + bb.y);
        }
    }
}

// ===========================================================================
// Attention (R11 verbatim): 128 q/CTA, 128 threads, occ 2, 2-stage K/V,
// online softmax, per-block chunk skip.
// ===========================================================================
#define ATQ      128
#define ANT      128
#define APB      144
#define ATILE_B  (64 * APB)
#define ASTAGE_B (4 * ATILE_B)
#define AQ_B     (128 * APB)
#define ATTN_SMEM (2 * ASTAGE_B)

__device__ __forceinline__ void aload_tile(const __nv_bfloat16* src, uint32_t dst, int t)
{
#pragma unroll
    for (int it = 0; it < 4; it++) {
        int idx = t + it * ANT;
        int row = idx >> 3, c = idx & 7;
        CPA16(dst + row * APB + c * 16, src + (size_t)row * HD_ + c * 8);
    }
}
__device__ __forceinline__ void aload_q(const __nv_bfloat16* src, uint32_t dst, int t)
{
#pragma unroll
    for (int it = 0; it < 8; it++) {
        int idx = t + it * ANT;
        int row = idx >> 3, c = idx & 7;
        CPA16(dst + row * APB + c * 16, src + (size_t)row * HD_ + c * 8);
    }
}

__device__ __forceinline__ void docpa(int j, const __nv_bfloat16* kh, const __nv_bfloat16* kl,
                                      const __nv_bfloat16* vh, const __nv_bfloat16* vl,
                                      uint32_t ns, int t)
{
    int tile = j >> 2;
    int idx  = t + (j & 3) * ANT;
    int row = idx >> 3, c = idx & 7;
    const __nv_bfloat16* src = (tile == 0) ? kh : (tile == 1) ? kl : (tile == 2) ? vh : vl;
    CPA16(ns + tile * ATILE_B + row * APB + c * 16, src + (size_t)row * HD_ + c * 8);
}

__device__ __forceinline__ void attn_block(
    uint32_t ks, int kc, int row0,
    const uint32_t (*qh)[4], const uint32_t (*ql)[4],
    float* m_, float* l_, float (*oacc)[4],
    bool dopf,
    const __nv_bfloat16* kh, const __nv_bfloat16* kl,
    const __nv_bfloat16* vh, const __nv_bfloat16* vl,
    uint32_t ns, int t, int lane, int g, int tq)
{
    float sacc[8][4];
#pragma unroll
    for (int j = 0; j < 8; j++)
#pragma unroll
        for (int cc = 0; cc < 4; cc++) sacc[j][cc] = 0.f;

#pragma unroll
    for (int kc2 = 0; kc2 < 4; kc2++) {
#pragma unroll
        for (int jp = 0; jp < 4; jp++) {
            int r = jp * 16 + (lane >> 4) * 8 + (lane & 7);
            uint32_t a = ks + r * APB + kc2 * 32 + ((lane >> 3) & 1) * 16;
            uint32_t bh0[2], bh1[2], bl0[2], bl1[2];
            LDSM4(bh0[0], bh0[1], bh1[0], bh1[1], a);
            LDSM4(bl0[0], bl0[1], bl1[0], bl1[1], a + ATILE_B);
            mma_bf16(sacc[2*jp],   qh[kc2], bh0);
            mma_bf16(sacc[2*jp],   ql[kc2], bh0);
            mma_bf16(sacc[2*jp],   qh[kc2], bl0);
            mma_bf16(sacc[2*jp+1], qh[kc2], bh1);
            mma_bf16(sacc[2*jp+1], ql[kc2], bh1);
            mma_bf16(sacc[2*jp+1], qh[kc2], bl1);
            int gi = kc2 * 4 + jp;
            if (dopf) docpa(gi, kh, kl, vh, vl, ns, t);
        }
    }

#pragma unroll
    for (int half = 0; half < 2; half++) {
        int row = row0 + 8 * half;
        float mx = -INFINITY;
#pragma unroll
        for (int j = 0; j < 8; j++) {
            int col = kc + 8 * j + 2 * tq;
            float v0 = sacc[j][2 * half];
            float v1 = sacc[j][2 * half + 1];
            int d0 = row - col;     d0 = d0 < 0 ? -d0 : d0;
            int d1 = row - col - 1; d1 = d1 < 0 ? -d1 : d1;
            v0 = (d0 <= WIN) ? v0 * SCALE : -INFINITY;
            v1 = (d1 <= WIN) ? v1 * SCALE : -INFINITY;
            sacc[j][2 * half]     = v0;
            sacc[j][2 * half + 1] = v1;
            mx = fmaxf(mx, fmaxf(v0, v1));
        }
        mx = fmaxf(mx, __shfl_xor_sync(0xffffffffu, mx, 1, 4));
        mx = fmaxf(mx, __shfl_xor_sync(0xffffffffu, mx, 2, 4));

        float mn    = fmaxf(m_[half], mx);
        float msafe = (mn == -INFINITY) ? 0.f : mn;
        float alpha = __expf(m_[half] - msafe);
        m_[half] = mn;

        float rs = 0.f;
#pragma unroll
        for (int j = 0; j < 8; j++) {
            float p0 = __expf(sacc[j][2 * half]     - msafe);
            float p1 = __expf(sacc[j][2 * half + 1] - msafe);
            sacc[j][2 * half]     = p0;
            sacc[j][2 * half + 1] = p1;
            rs += p0 + p1;
        }
        rs += __shfl_xor_sync(0xffffffffu, rs, 1, 4);
        rs += __shfl_xor_sync(0xffffffffu, rs, 2, 4);
        l_[half] = l_[half] * alpha + rs;
#pragma unroll
        for (int j = 0; j < 8; j++) {
            oacc[j][2 * half]     *= alpha;
            oacc[j][2 * half + 1] *= alpha;
        }
    }

#pragma unroll
    for (int kp = 0; kp < 4; kp++) {
        uint32_t ph[4], pl[4];
        split2(sacc[2*kp][0],   sacc[2*kp][1],   ph[0], pl[0]);
        split2(sacc[2*kp][2],   sacc[2*kp][3],   ph[1], pl[1]);
        split2(sacc[2*kp+1][0], sacc[2*kp+1][1], ph[2], pl[2]);
        split2(sacc[2*kp+1][2], sacc[2*kp+1][3], ph[3], pl[3]);

#pragma unroll
        for (int jp = 0; jp < 4; jp++) {
            int keyrow = kp * 16 + ((lane >> 3) & 1) * 8 + (lane & 7);
            uint32_t a = ks + 2 * ATILE_B + keyrow * APB + (2 * jp + (lane >> 4)) * 16;
            uint32_t vh0[2], vh1[2], vl0[2], vl1[2];
            LDSM4T(vh0[0], vh0[1], vh1[0], vh1[1], a);
            LDSM4T(vl0[0], vl0[1], vl1[0], vl1[1], a + ATILE_B);
            mma_bf16(oacc[2*jp],   ph, vh0);
            mma_bf16(oacc[2*jp],   pl, vh0);
            mma_bf16(oacc[2*jp],   ph, vl0);
            mma_bf16(oacc[2*jp+1], ph, vh1);
            mma_bf16(oacc[2*jp+1], pl, vh1);
            mma_bf16(oacc[2*jp+1], ph, vl1);
        }
    }
}

__global__ __launch_bounds__(ANT, 2) void attn_k()
{
    extern __shared__ char sma[];
    uint32_t sb = scvta(sma);

    const int t    = threadIdx.x;
    const int lane = t & 31;
    const int w    = t >> 5;
    const int g    = lane >> 2;
    const int tq   = lane & 3;

    const int q0 = blockIdx.x * ATQ;
    const int h  = blockIdx.y;
    const int b  = blockIdx.z;
    const size_t hb = (size_t)(b * NH + h) * S_ * HD_;

    int kc0 = q0 - WIN; if (kc0 < 0) kc0 = 0;
    int kce = q0 + ATQ + WIN; if (kce > S_) kce = S_;
    const int nch = (kce - kc0) >> 6;

    aload_q(gq_h + hb + (size_t)q0 * HD_, sb,        t);
    aload_q(gq_l + hb + (size_t)q0 * HD_, sb + AQ_B, t);
    CPC();
    CPW(0);
    __syncthreads();

    uint32_t qh[2][4][4], ql[2][4][4];
#pragma unroll
    for (int blk = 0; blk < 2; blk++) {
        int r = 32 * w + 16 * blk + (lane & 15);
#pragma unroll
        for (int kc = 0; kc < 4; kc++) {
            uint32_t a = sb + r * APB + kc * 32 + (lane >> 4) * 16;
            LDSM4(qh[blk][kc][0], qh[blk][kc][1], qh[blk][kc][2], qh[blk][kc][3], a);
            LDSM4(ql[blk][kc][0], ql[blk][kc][1], ql[blk][kc][2], ql[blk][kc][3], a + AQ_B);
        }
    }
    __syncthreads();

    {
        size_t off = hb + (size_t)kc0 * HD_;
        aload_tile(gk_h + off, sb,               t);
        aload_tile(gk_l + off, sb + ATILE_B,     t);
        aload_tile(gv_h + off, sb + 2 * ATILE_B, t);
        aload_tile(gv_l + off, sb + 3 * ATILE_B, t);
    }
    CPC();

    float oacc[2][8][4];
#pragma unroll
    for (int blk = 0; blk < 2; blk++)
#pragma unroll
        for (int j = 0; j < 8; j++)
#pragma unroll
            for (int c = 0; c < 4; c++) oacc[blk][j][c] = 0.f;
    float m_[2][2] = {{-INFINITY, -INFINITY}, {-INFINITY, -INFINITY}};
    float l_[2][2] = {{0.f, 0.f}, {0.f, 0.f}};

    const int qlo0 = q0 + 32 * w;
    const int qlo1 = qlo0 + 16;

    for (int c = 0; c < nch; c++) {
        const int kc = kc0 + c * 64;
        CPW(0);
        __syncthreads();
        const uint32_t ks = sb + (c & 1) * ASTAGE_B;
        const uint32_t ns = sb + ((c + 1) & 1) * ASTAGE_B;
        const bool pf = (c + 1 < nch);
        const size_t noff = hb + (size_t)(kc + 64) * HD_;
        const __nv_bfloat16 *kh = gk_h + noff, *kl = gk_l + noff;
        const __nv_bfloat16 *vh = gv_h + noff, *vl = gv_l + noff;

        bool a0 = (kc + 64 > qlo0 - WIN) && (kc <= qlo0 + 15 + WIN);
        bool a1 = (kc + 64 > qlo1 - WIN) && (kc <= qlo1 + 15 + WIN);

        if (pf && !a0) {
#pragma unroll
            for (int j = 0; j < 16; j++) docpa(j, kh, kl, vh, vl, ns, t);
        }
        if (a0)
            attn_block(ks, kc, qlo0 + g, qh[0], ql[0], m_[0], l_[0], oacc[0],
                       pf, kh, kl, vh, vl, ns, t, lane, g, tq);
        if (a1)
            attn_block(ks, kc, qlo1 + g, qh[1], ql[1], m_[1], l_[1], oacc[1],
                       false, kh, kl, vh, vl, ns, t, lane, g, tq);
        CPC();
    }

#pragma unroll
    for (int blk = 0; blk < 2; blk++) {
        int row0 = q0 + 32 * w + 16 * blk + g;
        float rl0 = 1.f / l_[blk][0];
        float rl1 = 1.f / l_[blk][1];
        size_t c0 = ((size_t)b * S_ + row0) * DOUT + h * HD_;
        size_t c1 = c0 + 8 * DOUT;
#pragma unroll
        for (int j = 0; j < 8; j++) {
            int hd = 8 * j + 2 * tq;
            uint32_t hw, lw;
            split2(oacc[blk][j][0] * rl0, oacc[blk][j][1] * rl0, hw, lw);
            *(uint32_t*)(gc_h + c0 + hd) = hw;
            *(uint32_t*)(gc_l + c0 + hd) = lw;
            split2(oacc[blk][j][2] * rl1, oacc[blk][j][3] * rl1, hw, lw);
            *(uint32_t*)(gc_h + c1 + hd) = hw;
            *(uint32_t*)(gc_l + c1 + hd) = lw;
        }
    }
}

// ===========================================================================
extern "C" void kernel_launch(void* const* d_in, const int* in_sizes, int n_in,
                              void* d_out, int out_size)
{
    const float* x    = (const float*)d_in[0];
    const float* wqkv = (const float*)d_in[1];
    const float* wout = (const float*)d_in[2];
    const float* bout = (const float*)d_in[3];
    float* out = (float*)d_out;

    cudaFuncSetAttribute(qkv_gemm_k, cudaFuncAttributeMaxDynamicSharedMemorySize, GEMM_SMEM);
    cudaFuncSetAttribute(out_gemm_k, cudaFuncAttributeMaxDynamicSharedMemorySize, GEMM_SMEM);
    cudaFuncSetAttribute(attn_k, cudaFuncAttributeMaxDynamicSharedMemorySize, ATTN_SMEM);

    split_all_kernel<<<N4_ALL / 256, 256>>>((const float4*)x, (const float4*)wqkv,
                                            (const float4*)wout);

    qkv_gemm_k<<<dim3(3 * DOUT / 256, (B_ * S_) / 128), 256, GEMM_SMEM>>>();
    attn_k<<<dim3(S_ / ATQ, NH, B_), ANT, ATTN_SMEM>>>();
    out_gemm_k<<<dim3(DOUT / 256, (B_ * S_) / 128), 256, GEMM_SMEM>>>(bout, out);
}

// round 16
// speedup vs baseline: 1.0402x; 1.0402x over previous
#include <cuda_runtime.h>
#include <cuda_bf16.h>
#include <math.h>
#include <stdint.h>

#define B_    2
#define S_    2048
#define DIN   1024
#define DOUT  1024
#define NH    16
#define HD_   64
#define WIN   256
#define SCALE 0.125f

#define NQKV (B_*NH*S_*HD_)
#define NX   (B_*S_*DIN)

__device__ __align__(16) __nv_bfloat16 gx_h[NX],  gx_l[NX];
__device__ __align__(16) __nv_bfloat16 gwq_h[3*DOUT*DIN], gwq_l[3*DOUT*DIN];
__device__ __align__(16) __nv_bfloat16 gwo_h[DOUT*DOUT],  gwo_l[DOUT*DOUT];
__device__ __align__(16) __nv_bfloat16 gq_h[NQKV], gq_l[NQKV];
__device__ __align__(16) __nv_bfloat16 gk_h[NQKV], gk_l[NQKV];
__device__ __align__(16) __nv_bfloat16 gv_h[NQKV], gv_l[NQKV];
__device__ __align__(16) __nv_bfloat16 gc_h[B_*S_*DOUT], gc_l[B_*S_*DOUT];

// ===========================================================================
__device__ __forceinline__ void split2(float x, float y, uint32_t& hi, uint32_t& lo) {
    __nv_bfloat16 hx = __float2bfloat16(x);
    __nv_bfloat16 hy = __float2bfloat16(y);
    float rx = x - __bfloat162float(hx);
    float ry = y - __bfloat162float(hy);
    __nv_bfloat16 lx = __float2bfloat16(rx);
    __nv_bfloat16 ly = __float2bfloat16(ry);
    __nv_bfloat162 hv; hv.x = hx; hv.y = hy;
    __nv_bfloat162 lv; lv.x = lx; lv.y = ly;
    hi = *(uint32_t*)&hv;
    lo = *(uint32_t*)&lv;
}

__device__ __forceinline__ void mma_bf16(float c[4], const uint32_t a[4], const uint32_t b[2]) {
    asm volatile(
        "mma.sync.aligned.m16n8k16.row.col.f32.bf16.bf16.f32 "
        "{%0,%1,%2,%3}, {%4,%5,%6,%7}, {%8,%9}, {%0,%1,%2,%3};"
        : "+f"(c[0]), "+f"(c[1]), "+f"(c[2]), "+f"(c[3])
        : "r"(a[0]), "r"(a[1]), "r"(a[2]), "r"(a[3]), "r"(b[0]), "r"(b[1]));
}

#define CPA16(dst, src) asm volatile("cp.async.cg.shared.global [%0], [%1], 16;" :: "r"(dst), "l"(src))
#define CPC()  asm volatile("cp.async.commit_group;" ::: "memory")
#define CPW(n) asm volatile("cp.async.wait_group %0;" :: "n"(n) : "memory")

#define LDSM4(d0,d1,d2,d3,a) \
    asm volatile("ldmatrix.sync.aligned.m8n8.x4.shared.b16 {%0,%1,%2,%3}, [%4];" \
                 : "=r"(d0),"=r"(d1),"=r"(d2),"=r"(d3) : "r"(a))
#define LDSM4T(d0,d1,d2,d3,a) \
    asm volatile("ldmatrix.sync.aligned.m8n8.x4.trans.shared.b16 {%0,%1,%2,%3}, [%4];" \
                 : "=r"(d0),"=r"(d1),"=r"(d2),"=r"(d3) : "r"(a))

__device__ __forceinline__ uint32_t scvta(const void* p) {
    return (uint32_t)__cvta_generic_to_shared(p);
}

// ===========================================================================
// Fused split (vectorized: 2 float4 in, 1 uint4 out per hi/lo array).
// ===========================================================================
#define N8_X   (NX / 8)                    // 524288
#define N8_WQ  (3 * DOUT * DIN / 8)        // 393216
#define N8_WO  (DOUT * DOUT / 8)           // 131072
#define N8_ALL (N8_X + N8_WQ + N8_WO)      // 1048576

__global__ void split_all_kernel(const float4* __restrict__ x,
                                 const float4* __restrict__ wq,
                                 const float4* __restrict__ wo)
{
    int i = blockIdx.x * 256 + threadIdx.x;
    const float4* src;
    uint4 *hi, *lo;
    int j;
    if (i < N8_X) {
        src = x;  j = i;
        hi = (uint4*)gx_h;  lo = (uint4*)gx_l;
    } else if (i < N8_X + N8_WQ) {
        src = wq; j = i - N8_X;
        hi = (uint4*)gwq_h; lo = (uint4*)gwq_l;
    } else {
        src = wo; j = i - N8_X - N8_WQ;
        hi = (uint4*)gwo_h; lo = (uint4*)gwo_l;
    }
    float4 v0 = src[2 * j];
    float4 v1 = src[2 * j + 1];
    uint4 h, l;
    split2(v0.x, v0.y, h.x, l.x);
    split2(v0.z, v0.w, h.y, l.y);
    split2(v1.x, v1.y, h.z, l.z);
    split2(v1.z, v1.w, h.w, l.w);
    hi[j] = h;
    lo[j] = l;
}

// ===========================================================================
// GEMM (R11 verbatim): C[128x256]/CTA, 8 warps, 64x64 warp tile, BK=64,
// 2-stage cp.async, bf16 3-pass, interleaved cps/LDSM, per-kc prefix.
// ===========================================================================
#define PRB       144
#define GA_B      (128 * PRB)
#define GB_B      (256 * PRB)
#define GSTAGE_B  (2 * GA_B + 2 * GB_B)
#define GOFF_AL   GA_B
#define GOFF_BH   (2 * GA_B)
#define GOFF_BL   (GOFF_BH + GB_B)
#define GEMM_SMEM (2 * GSTAGE_B)

__device__ __forceinline__ void gstage(const __nv_bfloat16* Ah, const __nv_bfloat16* Al,
                                       const __nv_bfloat16* Bh, const __nv_bfloat16* Bl,
                                       int k0, uint32_t sb, int t)
{
#pragma unroll
    for (int it = 0; it < 4; it++) {
        int idx = t + it * 256;
        int row = idx >> 3, c = idx & 7;
        uint32_t d = sb + row * PRB + c * 16;
        CPA16(d,           Ah + (size_t)row * 1024 + k0 + c * 8);
        CPA16(d + GOFF_AL, Al + (size_t)row * 1024 + k0 + c * 8);
    }
#pragma unroll
    for (int it = 0; it < 8; it++) {
        int idx = t + it * 256;
        int row = idx >> 3, c = idx & 7;
        uint32_t d = sb + GOFF_BH + row * PRB + c * 16;
        CPA16(d,        Bh + (size_t)row * 1024 + k0 + c * 8);
        CPA16(d + GB_B, Bl + (size_t)row * 1024 + k0 + c * 8);
    }
}

__device__ __forceinline__ void docp(int j,
                                     const __nv_bfloat16* Ah, const __nv_bfloat16* Al,
                                     const __nv_bfloat16* Bh, const __nv_bfloat16* Bl,
                                     int k0, uint32_t sb, int t)
{
    if (j < 8) {
        int it = j & 3;
        int idx = t + it * 256;
        int row = idx >> 3, c = idx & 7;
        uint32_t d = sb + row * PRB + c * 16;
        if (j < 4) CPA16(d,           Ah + (size_t)row * 1024 + k0 + c * 8);
        else       CPA16(d + GOFF_AL, Al + (size_t)row * 1024 + k0 + c * 8);
    } else {
        int jj = j - 8;
        int it = jj & 7;
        int idx = t + it * 256;
        int row = idx >> 3, c = idx & 7;
        uint32_t d = sb + GOFF_BH + row * PRB + c * 16;
        if (jj < 8) CPA16(d,        Bh + (size_t)row * 1024 + k0 + c * 8);
        else        CPA16(d + GB_B, Bl + (size_t)row * 1024 + k0 + c * 8);
    }
}

__device__ __forceinline__ void mma_g8(float (*accr)[4], const uint32_t a[4],
                                       const uint32_t (*b)[2])
{
#pragma unroll
    for (int j = 0; j < 8; j++) mma_bf16(accr[j], a, b[j]);
}

__device__ __forceinline__ void gemm_main(const __nv_bfloat16* Ah, const __nv_bfloat16* Al,
                                          const __nv_bfloat16* Bh, const __nv_bfloat16* Bl,
                                          uint32_t sb, float acc[4][8][4])
{
    const int t = threadIdx.x;
    const int lane = t & 31, wid = t >> 5;
    const int wm = wid >> 2, wn = wid & 3;

#pragma unroll
    for (int i = 0; i < 4; i++)
#pragma unroll
        for (int j = 0; j < 8; j++)
#pragma unroll
            for (int c = 0; c < 4; c++) acc[i][j][c] = 0.f;

    gstage(Ah, Al, Bh, Bl, 0, sb, t);
    CPC();

    for (int ks = 0; ks < 16; ks++) {
        CPW(0);
        __syncthreads();
        const uint32_t cs = sb + (ks & 1) * GSTAGE_B;
        const uint32_t ps = sb + ((ks + 1) & 1) * GSTAGE_B;
        const int k0n = (ks + 1) * 64;
        const bool pf = (ks < 15);

#pragma unroll
        for (int kc = 0; kc < 4; kc++) {
            uint32_t ah[4][4], al[4][4], bh[8][2], bl[8][2];
#pragma unroll
            for (int jp = 0; jp < 4; jp++) {
                int r = wn * 64 + jp * 16 + (lane >> 4) * 8 + (lane & 7);
                uint32_t a = cs + GOFF_BH + r * PRB + kc * 32 + ((lane >> 3) & 1) * 16;
                LDSM4(bh[2*jp][0], bh[2*jp][1], bh[2*jp+1][0], bh[2*jp+1][1], a);
            }
#pragma unroll
            for (int i = 0; i < 4; i++) {
                int r = wm * 64 + i * 16 + (lane & 15);
                LDSM4(ah[i][0], ah[i][1], ah[i][2], ah[i][3],
                      cs + r * PRB + kc * 32 + (lane >> 4) * 16);
            }
#pragma unroll
            for (int i = 0; i < 4; i++) {
                mma_g8(acc[i], ah[i], bh);
                int r = wm * 64 + i * 16 + (lane & 15);
                LDSM4(al[i][0], al[i][1], al[i][2], al[i][3],
                      cs + GOFF_AL + r * PRB + kc * 32 + (lane >> 4) * 16);
                int gi = kc * 12 + i;
                if (pf && gi < 24) docp(gi, Ah, Al, Bh, Bl, k0n, ps, t);
            }
#pragma unroll
            for (int i = 0; i < 4; i++) {
                mma_g8(acc[i], al[i], bh);
                int r = wn * 64 + i * 16 + (lane >> 4) * 8 + (lane & 7);
                uint32_t a = cs + GOFF_BL + r * PRB + kc * 32 + ((lane >> 3) & 1) * 16;
                LDSM4(bl[2*i][0], bl[2*i][1], bl[2*i+1][0], bl[2*i+1][1], a);
                int gi = kc * 12 + 4 + i;
                if (pf && gi < 24) docp(gi, Ah, Al, Bh, Bl, k0n, ps, t);
            }
#pragma unroll
            for (int i = 0; i < 4; i++) {
                mma_g8(acc[i], ah[i], bl);
                int gi = kc * 12 + 8 + i;
                if (pf && gi < 24) docp(gi, Ah, Al, Bh, Bl, k0n, ps, t);
            }
        }
        CPC();
    }
}

__global__ __launch_bounds__(256, 1) void qkv_gemm_k()
{
    extern __shared__ char smg[];
    uint32_t sb = scvta(smg);
    const int m0 = blockIdx.y * 128;
    const int n0 = blockIdx.x * 256;

    float acc[4][8][4];
    gemm_main(gx_h + (size_t)m0 * 1024, gx_l + (size_t)m0 * 1024,
              gwq_h + (size_t)n0 * 1024, gwq_l + (size_t)n0 * 1024, sb, acc);

    const int t = threadIdx.x;
    const int lane = t & 31, wid = t >> 5;
    const int wm = wid >> 2, wn = wid & 3;
    const int g = lane >> 2, tq = lane & 3;

    const int which = n0 >> 10;
    __nv_bfloat16* dh = (which == 0) ? gq_h : (which == 1) ? gk_h : gv_h;
    __nv_bfloat16* dl = (which == 0) ? gq_l : (which == 1) ? gk_l : gv_l;
    const int h = ((n0 + wn * 64) >> 6) & (NH - 1);

#pragma unroll
    for (int i = 0; i < 4; i++) {
        int m = m0 + wm * 64 + i * 16 + g;
        int b = m >> 11, s = m & (S_ - 1);
#pragma unroll
        for (int j = 0; j < 8; j++) {
            int hd = j * 8 + 2 * tq;
            size_t idx = (((size_t)(b * NH + h) * S_ + s) * HD_ + hd);
            uint32_t hw, lw;
            split2(acc[i][j][0], acc[i][j][1], hw, lw);
            *(uint32_t*)(dh + idx) = hw;
            *(uint32_t*)(dl + idx) = lw;
            split2(acc[i][j][2], acc[i][j][3], hw, lw);
            *(uint32_t*)(dh + idx + 8 * HD_) = hw;
            *(uint32_t*)(dl + idx + 8 * HD_) = lw;
        }
    }
}

__global__ __launch_bounds__(256, 1) void out_gemm_k(const float* __restrict__ bias,
                                                     float* __restrict__ out)
{
    extern __shared__ char smg[];
    uint32_t sb = scvta(smg);
    const int m0 = blockIdx.y * 128;
    const int n0 = blockIdx.x * 256;

    float acc[4][8][4];
    gemm_main(gc_h + (size_t)m0 * 1024, gc_l + (size_t)m0 * 1024,
              gwo_h + (size_t)n0 * 1024, gwo_l + (size_t)n0 * 1024, sb, acc);

    const int t = threadIdx.x;
    const int lane = t & 31, wid = t >> 5;
    const int wm = wid >> 2, wn = wid & 3;
    const int g = lane >> 2, tq = lane & 3;

#pragma unroll
    for (int i = 0; i < 4; i++) {
        int m = m0 + wm * 64 + i * 16 + g;
#pragma unroll
        for (int j = 0; j < 8; j++) {
            int nn = n0 + wn * 64 + j * 8 + 2 * tq;
            float2 bb = *(const float2*)(bias + nn);
            float* p = out + (size_t)m * DOUT + nn;
            *(float2*)p              = make_float2(acc[i][j][0] + bb.x, acc[i][j][1] + bb.y);
            *(float2*)(p + 8 * DOUT) = make_float2(acc[i][j][2] + bb.x, acc[i][j][3] + bb.y);
        }
    }
}

// ===========================================================================
// Attention (R11 verbatim): 128 q/CTA, 128 threads, occ 2, 2-stage K/V,
// online softmax, per-block chunk skip.
// ===========================================================================
#define ATQ      128
#define ANT      128
#define APB      144
#define ATILE_B  (64 * APB)
#define ASTAGE_B (4 * ATILE_B)
#define AQ_B     (128 * APB)
#define ATTN_SMEM (2 * ASTAGE_B)

__device__ __forceinline__ void aload_tile(const __nv_bfloat16* src, uint32_t dst, int t)
{
#pragma unroll
    for (int it = 0; it < 4; it++) {
        int idx = t + it * ANT;
        int row = idx >> 3, c = idx & 7;
        CPA16(dst + row * APB + c * 16, src + (size_t)row * HD_ + c * 8);
    }
}
__device__ __forceinline__ void aload_q(const __nv_bfloat16* src, uint32_t dst, int t)
{
#pragma unroll
    for (int it = 0; it < 8; it++) {
        int idx = t + it * ANT;
        int row = idx >> 3, c = idx & 7;
        CPA16(dst + row * APB + c * 16, src + (size_t)row * HD_ + c * 8);
    }
}

__device__ __forceinline__ void docpa(int j, const __nv_bfloat16* kh, const __nv_bfloat16* kl,
                                      const __nv_bfloat16* vh, const __nv_bfloat16* vl,
                                      uint32_t ns, int t)
{
    int tile = j >> 2;
    int idx  = t + (j & 3) * ANT;
    int row = idx >> 3, c = idx & 7;
    const __nv_bfloat16* src = (tile == 0) ? kh : (tile == 1) ? kl : (tile == 2) ? vh : vl;
    CPA16(ns + tile * ATILE_B + row * APB + c * 16, src + (size_t)row * HD_ + c * 8);
}

__device__ __forceinline__ void attn_block(
    uint32_t ks, int kc, int row0,
    const uint32_t (*qh)[4], const uint32_t (*ql)[4],
    float* m_, float* l_, float (*oacc)[4],
    bool dopf,
    const __nv_bfloat16* kh, const __nv_bfloat16* kl,
    const __nv_bfloat16* vh, const __nv_bfloat16* vl,
    uint32_t ns, int t, int lane, int g, int tq)
{
    float sacc[8][4];
#pragma unroll
    for (int j = 0; j < 8; j++)
#pragma unroll
        for (int cc = 0; cc < 4; cc++) sacc[j][cc] = 0.f;

#pragma unroll
    for (int kc2 = 0; kc2 < 4; kc2++) {
#pragma unroll
        for (int jp = 0; jp < 4; jp++) {
            int r = jp * 16 + (lane >> 4) * 8 + (lane & 7);
            uint32_t a = ks + r * APB + kc2 * 32 + ((lane >> 3) & 1) * 16;
            uint32_t bh0[2], bh1[2], bl0[2], bl1[2];
            LDSM4(bh0[0], bh0[1], bh1[0], bh1[1], a);
            LDSM4(bl0[0], bl0[1], bl1[0], bl1[1], a + ATILE_B);
            mma_bf16(sacc[2*jp],   qh[kc2], bh0);
            mma_bf16(sacc[2*jp],   ql[kc2], bh0);
            mma_bf16(sacc[2*jp],   qh[kc2], bl0);
            mma_bf16(sacc[2*jp+1], qh[kc2], bh1);
            mma_bf16(sacc[2*jp+1], ql[kc2], bh1);
            mma_bf16(sacc[2*jp+1], qh[kc2], bl1);
            int gi = kc2 * 4 + jp;
            if (dopf) docpa(gi, kh, kl, vh, vl, ns, t);
        }
    }

#pragma unroll
    for (int half = 0; half < 2; half++) {
        int row = row0 + 8 * half;
        float mx = -INFINITY;
#pragma unroll
        for (int j = 0; j < 8; j++) {
            int col = kc + 8 * j + 2 * tq;
            float v0 = sacc[j][2 * half];
            float v1 = sacc[j][2 * half + 1];
            int d0 = row - col;     d0 = d0 < 0 ? -d0 : d0;
            int d1 = row - col - 1; d1 = d1 < 0 ? -d1 : d1;
            v0 = (d0 <= WIN) ? v0 * SCALE : -INFINITY;
            v1 = (d1 <= WIN) ? v1 * SCALE : -INFINITY;
            sacc[j][2 * half]     = v0;
            sacc[j][2 * half + 1] = v1;
            mx = fmaxf(mx, fmaxf(v0, v1));
        }
        mx = fmaxf(mx, __shfl_xor_sync(0xffffffffu, mx, 1, 4));
        mx = fmaxf(mx, __shfl_xor_sync(0xffffffffu, mx, 2, 4));

        float mn    = fmaxf(m_[half], mx);
        float msafe = (mn == -INFINITY) ? 0.f : mn;
        float alpha = __expf(m_[half] - msafe);
        m_[half] = mn;

        float rs = 0.f;
#pragma unroll
        for (int j = 0; j < 8; j++) {
            float p0 = __expf(sacc[j][2 * half]     - msafe);
            float p1 = __expf(sacc[j][2 * half + 1] - msafe);
            sacc[j][2 * half]     = p0;
            sacc[j][2 * half + 1] = p1;
            rs += p0 + p1;
        }
        rs += __shfl_xor_sync(0xffffffffu, rs, 1, 4);
        rs += __shfl_xor_sync(0xffffffffu, rs, 2, 4);
        l_[half] = l_[half] * alpha + rs;
#pragma unroll
        for (int j = 0; j < 8; j++) {
            oacc[j][2 * half]     *= alpha;
            oacc[j][2 * half + 1] *= alpha;
        }
    }

#pragma unroll
    for (int kp = 0; kp < 4; kp++) {
        uint32_t ph[4], pl[4];
        split2(sacc[2*kp][0],   sacc[2*kp][1],   ph[0], pl[0]);
        split2(sacc[2*kp][2],   sacc[2*kp][3],   ph[1], pl[1]);
        split2(sacc[2*kp+1][0], sacc[2*kp+1][1], ph[2], pl[2]);
        split2(sacc[2*kp+1][2], sacc[2*kp+1][3], ph[3], pl[3]);

#pragma unroll
        for (int jp = 0; jp < 4; jp++) {
            int keyrow = kp * 16 + ((lane >> 3) & 1) * 8 + (lane & 7);
            uint32_t a = ks + 2 * ATILE_B + keyrow * APB + (2 * jp + (lane >> 4)) * 16;
            uint32_t vh0[2], vh1[2], vl0[2], vl1[2];
            LDSM4T(vh0[0], vh0[1], vh1[0], vh1[1], a);
            LDSM4T(vl0[0], vl0[1], vl1[0], vl1[1], a + ATILE_B);
            mma_bf16(oacc[2*jp],   ph, vh0);
            mma_bf16(oacc[2*jp],   pl, vh0);
            mma_bf16(oacc[2*jp],   ph, vl0);
            mma_bf16(oacc[2*jp+1], ph, vh1);
            mma_bf16(oacc[2*jp+1], pl, vh1);
            mma_bf16(oacc[2*jp+1], ph, vl1);
        }
    }
}

__global__ __launch_bounds__(ANT, 2) void attn_k()
{
    extern __shared__ char sma[];
    uint32_t sb = scvta(sma);

    const int t    = threadIdx.x;
    const int lane = t & 31;
    const int w    = t >> 5;
    const int g    = lane >> 2;
    const int tq   = lane & 3;

    const int q0 = blockIdx.x * ATQ;
    const int h  = blockIdx.y;
    const int b  = blockIdx.z;
    const size_t hb = (size_t)(b * NH + h) * S_ * HD_;

    int kc0 = q0 - WIN; if (kc0 < 0) kc0 = 0;
    int kce = q0 + ATQ + WIN; if (kce > S_) kce = S_;
    const int nch = (kce - kc0) >> 6;

    aload_q(gq_h + hb + (size_t)q0 * HD_, sb,        t);
    aload_q(gq_l + hb + (size_t)q0 * HD_, sb + AQ_B, t);
    CPC();
    CPW(0);
    __syncthreads();

    uint32_t qh[2][4][4], ql[2][4][4];
#pragma unroll
    for (int blk = 0; blk < 2; blk++) {
        int r = 32 * w + 16 * blk + (lane & 15);
#pragma unroll
        for (int kc = 0; kc < 4; kc++) {
            uint32_t a = sb + r * APB + kc * 32 + (lane >> 4) * 16;
            LDSM4(qh[blk][kc][0], qh[blk][kc][1], qh[blk][kc][2], qh[blk][kc][3], a);
            LDSM4(ql[blk][kc][0], ql[blk][kc][1], ql[blk][kc][2], ql[blk][kc][3], a + AQ_B);
        }
    }
    __syncthreads();

    {
        size_t off = hb + (size_t)kc0 * HD_;
        aload_tile(gk_h + off, sb,               t);
        aload_tile(gk_l + off, sb + ATILE_B,     t);
        aload_tile(gv_h + off, sb + 2 * ATILE_B, t);
        aload_tile(gv_l + off, sb + 3 * ATILE_B, t);
    }
    CPC();

    float oacc[2][8][4];
#pragma unroll
    for (int blk = 0; blk < 2; blk++)
#pragma unroll
        for (int j = 0; j < 8; j++)
#pragma unroll
            for (int c = 0; c < 4; c++) oacc[blk][j][c] = 0.f;
    float m_[2][2] = {{-INFINITY, -INFINITY}, {-INFINITY, -INFINITY}};
    float l_[2][2] = {{0.f, 0.f}, {0.f, 0.f}};

    const int qlo0 = q0 + 32 * w;
    const int qlo1 = qlo0 + 16;

    for (int c = 0; c < nch; c++) {
        const int kc = kc0 + c * 64;
        CPW(0);
        __syncthreads();
        const uint32_t ks = sb + (c & 1) * ASTAGE_B;
        const uint32_t ns = sb + ((c + 1) & 1) * ASTAGE_B;
        const bool pf = (c + 1 < nch);
        const size_t noff = hb + (size_t)(kc + 64) * HD_;
        const __nv_bfloat16 *kh = gk_h + noff, *kl = gk_l + noff;
        const __nv_bfloat16 *vh = gv_h + noff, *vl = gv_l + noff;

        bool a0 = (kc + 64 > qlo0 - WIN) && (kc <= qlo0 + 15 + WIN);
        bool a1 = (kc + 64 > qlo1 - WIN) && (kc <= qlo1 + 15 + WIN);

        if (pf && !a0) {
#pragma unroll
            for (int j = 0; j < 16; j++) docpa(j, kh, kl, vh, vl, ns, t);
        }
        if (a0)
            attn_block(ks, kc, qlo0 + g, qh[0], ql[0], m_[0], l_[0], oacc[0],
                       pf, kh, kl, vh, vl, ns, t, lane, g, tq);
        if (a1)
            attn_block(ks, kc, qlo1 + g, qh[1], ql[1], m_[1], l_[1], oacc[1],
                       false, kh, kl, vh, vl, ns, t, lane, g, tq);
        CPC();
    }

#pragma unroll
    for (int blk = 0; blk < 2; blk++) {
        int row0 = q0 + 32 * w + 16 * blk + g;
        float rl0 = 1.f / l_[blk][0];
        float rl1 = 1.f / l_[blk][1];
        size_t c0 = ((size_t)b * S_ + row0) * DOUT + h * HD_;
        size_t c1 = c0 + 8 * DOUT;
#pragma unroll
        for (int j = 0; j < 8; j++) {
            int hd = 8 * j + 2 * tq;
            uint32_t hw, lw;
            split2(oacc[blk][j][0] * rl0, oacc[blk][j][1] * rl0, hw, lw);
            *(uint32_t*)(gc_h + c0 + hd) = hw;
            *(uint32_t*)(gc_l + c0 + hd) = lw;
            split2(oacc[blk][j][2] * rl1, oacc[blk][j][3] * rl1, hw, lw);
            *(uint32_t*)(gc_h + c1 + hd) = hw;
            *(uint32_t*)(gc_l + c1 + hd) = lw;
        }
    }
}

// ===========================================================================
extern "C" void kernel_launch(void* const* d_in, const int* in_sizes, int n_in,
                              void* d_out, int out_size)
{
    const float* x    = (const float*)d_in[0];
    const float* wqkv = (const float*)d_in[1];
    const float* wout = (const float*)d_in[2];
    const float* bout = (const float*)d_in[3];
    float* out = (float*)d_out;

    cudaFuncSetAttribute(qkv_gemm_k, cudaFuncAttributeMaxDynamicSharedMemorySize, GEMM_SMEM);
    cudaFuncSetAttribute(out_gemm_k, cudaFuncAttributeMaxDynamicSharedMemorySize, GEMM_SMEM);
    cudaFuncSetAttribute(attn_k, cudaFuncAttributeMaxDynamicSharedMemorySize, ATTN_SMEM);

    split_all_kernel<<<N8_ALL / 256, 256>>>((const float4*)x, (const float4*)wqkv,
                                            (const float4*)wout);

    qkv_gemm_k<<<dim3(3 * DOUT / 256, (B_ * S_) / 128), 256, GEMM_SMEM>>>();
    attn_k<<<dim3(S_ / ATQ, NH, B_), ANT, ATTN_SMEM>>>();
    out_gemm_k<<<dim3(DOUT / 256, (B_ * S_) / 128), 256, GEMM_SMEM>>>(bout, out);
}

// round 17
// speedup vs baseline: 1.0959x; 1.0535x over previous
#include <cuda_runtime.h>
#include <cuda_bf16.h>
#include <cuda_fp16.h>
#include <math.h>
#include <stdint.h>

#define B_    2
#define S_    2048
#define DIN   1024
#define DOUT  1024
#define NH    16
#define HD_   64
#define WIN   256
#define SCALE 0.125f

#define NQKV (B_*NH*S_*HD_)
#define NX   (B_*S_*DIN)

__device__ __align__(16) __nv_bfloat16 gx_h[NX],  gx_l[NX];
__device__ __align__(16) __nv_bfloat16 gwq_h[3*DOUT*DIN], gwq_l[3*DOUT*DIN];
__device__ __align__(16) __half        gwoh[DOUT*DOUT];
__device__ __align__(16) __nv_bfloat16 gq_h[NQKV], gq_l[NQKV];
__device__ __align__(16) __nv_bfloat16 gk_h[NQKV], gk_l[NQKV];
__device__ __align__(16) __nv_bfloat16 gv_h[NQKV], gv_l[NQKV];
__device__ __align__(16) __half        gc_h[B_*S_*DOUT], gc_l[B_*S_*DOUT];

// ===========================================================================
__device__ __forceinline__ void split2(float x, float y, uint32_t& hi, uint32_t& lo) {
    __nv_bfloat16 hx = __float2bfloat16(x);
    __nv_bfloat16 hy = __float2bfloat16(y);
    float rx = x - __bfloat162float(hx);
    float ry = y - __bfloat162float(hy);
    __nv_bfloat16 lx = __float2bfloat16(rx);
    __nv_bfloat16 ly = __float2bfloat16(ry);
    __nv_bfloat162 hv; hv.x = hx; hv.y = hy;
    __nv_bfloat162 lv; lv.x = lx; lv.y = ly;
    hi = *(uint32_t*)&hv;
    lo = *(uint32_t*)&lv;
}

__device__ __forceinline__ void split2h(float x, float y, uint32_t& hi, uint32_t& lo) {
    __half hx = __float2half(x);
    __half hy = __float2half(y);
    float rx = x - __half2float(hx);
    float ry = y - __half2float(hy);
    __half2 hv = __halves2half2(hx, hy);
    __half2 lv = __halves2half2(__float2half(rx), __float2half(ry));
    hi = *(uint32_t*)&hv;
    lo = *(uint32_t*)&lv;
}

__device__ __forceinline__ void mma_bf16(float c[4], const uint32_t a[4], const uint32_t b[2]) {
    asm volatile(
        "mma.sync.aligned.m16n8k16.row.col.f32.bf16.bf16.f32 "
        "{%0,%1,%2,%3}, {%4,%5,%6,%7}, {%8,%9}, {%0,%1,%2,%3};"
        : "+f"(c[0]), "+f"(c[1]), "+f"(c[2]), "+f"(c[3])
        : "r"(a[0]), "r"(a[1]), "r"(a[2]), "r"(a[3]), "r"(b[0]), "r"(b[1]));
}

__device__ __forceinline__ void mma_f16(float c[4], const uint32_t a[4], const uint32_t b[2]) {
    asm volatile(
        "mma.sync.aligned.m16n8k16.row.col.f32.f16.f16.f32 "
        "{%0,%1,%2,%3}, {%4,%5,%6,%7}, {%8,%9}, {%0,%1,%2,%3};"
        : "+f"(c[0]), "+f"(c[1]), "+f"(c[2]), "+f"(c[3])
        : "r"(a[0]), "r"(a[1]), "r"(a[2]), "r"(a[3]), "r"(b[0]), "r"(b[1]));
}

#define CPA16(dst, src) asm volatile("cp.async.cg.shared.global [%0], [%1], 16;" :: "r"(dst), "l"(src))
#define CPC()  asm volatile("cp.async.commit_group;" ::: "memory")
#define CPW(n) asm volatile("cp.async.wait_group %0;" :: "n"(n) : "memory")

#define LDSM4(d0,d1,d2,d3,a) \
    asm volatile("ldmatrix.sync.aligned.m8n8.x4.shared.b16 {%0,%1,%2,%3}, [%4];" \
                 : "=r"(d0),"=r"(d1),"=r"(d2),"=r"(d3) : "r"(a))
#define LDSM4T(d0,d1,d2,d3,a) \
    asm volatile("ldmatrix.sync.aligned.m8n8.x4.trans.shared.b16 {%0,%1,%2,%3}, [%4];" \
                 : "=r"(d0),"=r"(d1),"=r"(d2),"=r"(d3) : "r"(a))

__device__ __forceinline__ uint32_t scvta(const void* p) {
    return (uint32_t)__cvta_generic_to_shared(p);
}

// ===========================================================================
// Fused split: x, W_qkv -> bf16 hi/lo; W_out -> fp16 hi only.
// ===========================================================================
#define N8_X   (NX / 8)
#define N8_WQ  (3 * DOUT * DIN / 8)
#define N8_WO  (DOUT * DOUT / 8)
#define N8_ALL (N8_X + N8_WQ + N8_WO)

__global__ void split_all_kernel(const float4* __restrict__ x,
                                 const float4* __restrict__ wq,
                                 const float4* __restrict__ wo)
{
    int i = blockIdx.x * 256 + threadIdx.x;
    if (i < N8_X + N8_WQ) {
        const float4* src;
        uint4 *hi, *lo;
        int j;
        if (i < N8_X) {
            src = x;  j = i;
            hi = (uint4*)gx_h;  lo = (uint4*)gx_l;
        } else {
            src = wq; j = i - N8_X;
            hi = (uint4*)gwq_h; lo = (uint4*)gwq_l;
        }
        float4 v0 = src[2 * j];
        float4 v1 = src[2 * j + 1];
        uint4 h, l;
        split2(v0.x, v0.y, h.x, l.x);
        split2(v0.z, v0.w, h.y, l.y);
        split2(v1.x, v1.y, h.z, l.z);
        split2(v1.z, v1.w, h.w, l.w);
        hi[j] = h;
        lo[j] = l;
    } else {
        int j = i - N8_X - N8_WQ;
        float4 v0 = wo[2 * j];
        float4 v1 = wo[2 * j + 1];
        __half2 a = __floats2half2_rn(v0.x, v0.y);
        __half2 b = __floats2half2_rn(v0.z, v0.w);
        __half2 c = __floats2half2_rn(v1.x, v1.y);
        __half2 d = __floats2half2_rn(v1.z, v1.w);
        uint4 h;
        h.x = *(uint32_t*)&a; h.y = *(uint32_t*)&b;
        h.z = *(uint32_t*)&c; h.w = *(uint32_t*)&d;
        ((uint4*)gwoh)[j] = h;
    }
}

// ===========================================================================
// QKV GEMM (R11 verbatim, bf16 3-pass)
// ===========================================================================
#define PRB       144
#define GA_B      (128 * PRB)
#define GB_B      (256 * PRB)
#define GSTAGE_B  (2 * GA_B + 2 * GB_B)
#define GOFF_AL   GA_B
#define GOFF_BH   (2 * GA_B)
#define GOFF_BL   (GOFF_BH + GB_B)
#define GEMM_SMEM (2 * GSTAGE_B)

__device__ __forceinline__ void gstage(const __nv_bfloat16* Ah, const __nv_bfloat16* Al,
                                       const __nv_bfloat16* Bh, const __nv_bfloat16* Bl,
                                       int k0, uint32_t sb, int t)
{
#pragma unroll
    for (int it = 0; it < 4; it++) {
        int idx = t + it * 256;
        int row = idx >> 3, c = idx & 7;
        uint32_t d = sb + row * PRB + c * 16;
        CPA16(d,           Ah + (size_t)row * 1024 + k0 + c * 8);
        CPA16(d + GOFF_AL, Al + (size_t)row * 1024 + k0 + c * 8);
    }
#pragma unroll
    for (int it = 0; it < 8; it++) {
        int idx = t + it * 256;
        int row = idx >> 3, c = idx & 7;
        uint32_t d = sb + GOFF_BH + row * PRB + c * 16;
        CPA16(d,        Bh + (size_t)row * 1024 + k0 + c * 8);
        CPA16(d + GB_B, Bl + (size_t)row * 1024 + k0 + c * 8);
    }
}

__device__ __forceinline__ void docp(int j,
                                     const __nv_bfloat16* Ah, const __nv_bfloat16* Al,
                                     const __nv_bfloat16* Bh, const __nv_bfloat16* Bl,
                                     int k0, uint32_t sb, int t)
{
    if (j < 8) {
        int it = j & 3;
        int idx = t + it * 256;
        int row = idx >> 3, c = idx & 7;
        uint32_t d = sb + row * PRB + c * 16;
        if (j < 4) CPA16(d,           Ah + (size_t)row * 1024 + k0 + c * 8);
        else       CPA16(d + GOFF_AL, Al + (size_t)row * 1024 + k0 + c * 8);
    } else {
        int jj = j - 8;
        int it = jj & 7;
        int idx = t + it * 256;
        int row = idx >> 3, c = idx & 7;
        uint32_t d = sb + GOFF_BH + row * PRB + c * 16;
        if (jj < 8) CPA16(d,        Bh + (size_t)row * 1024 + k0 + c * 8);
        else        CPA16(d + GB_B, Bl + (size_t)row * 1024 + k0 + c * 8);
    }
}

__device__ __forceinline__ void mma_g8(float (*accr)[4], const uint32_t a[4],
                                       const uint32_t (*b)[2])
{
#pragma unroll
    for (int j = 0; j < 8; j++) mma_bf16(accr[j], a, b[j]);
}

__device__ __forceinline__ void mma_g8h(float (*accr)[4], const uint32_t a[4],
                                        const uint32_t (*b)[2])
{
#pragma unroll
    for (int j = 0; j < 8; j++) mma_f16(accr[j], a, b[j]);
}

__device__ __forceinline__ void gemm_main(const __nv_bfloat16* Ah, const __nv_bfloat16* Al,
                                          const __nv_bfloat16* Bh, const __nv_bfloat16* Bl,
                                          uint32_t sb, float acc[4][8][4])
{
    const int t = threadIdx.x;
    const int lane = t & 31, wid = t >> 5;
    const int wm = wid >> 2, wn = wid & 3;

#pragma unroll
    for (int i = 0; i < 4; i++)
#pragma unroll
        for (int j = 0; j < 8; j++)
#pragma unroll
            for (int c = 0; c < 4; c++) acc[i][j][c] = 0.f;

    gstage(Ah, Al, Bh, Bl, 0, sb, t);
    CPC();

    for (int ks = 0; ks < 16; ks++) {
        CPW(0);
        __syncthreads();
        const uint32_t cs = sb + (ks & 1) * GSTAGE_B;
        const uint32_t ps = sb + ((ks + 1) & 1) * GSTAGE_B;
        const int k0n = (ks + 1) * 64;
        const bool pf = (ks < 15);

#pragma unroll
        for (int kc = 0; kc < 4; kc++) {
            uint32_t ah[4][4], al[4][4], bh[8][2], bl[8][2];
#pragma unroll
            for (int jp = 0; jp < 4; jp++) {
                int r = wn * 64 + jp * 16 + (lane >> 4) * 8 + (lane & 7);
                uint32_t a = cs + GOFF_BH + r * PRB + kc * 32 + ((lane >> 3) & 1) * 16;
                LDSM4(bh[2*jp][0], bh[2*jp][1], bh[2*jp+1][0], bh[2*jp+1][1], a);
            }
#pragma unroll
            for (int i = 0; i < 4; i++) {
                int r = wm * 64 + i * 16 + (lane & 15);
                LDSM4(ah[i][0], ah[i][1], ah[i][2], ah[i][3],
                      cs + r * PRB + kc * 32 + (lane >> 4) * 16);
            }
#pragma unroll
            for (int i = 0; i < 4; i++) {
                mma_g8(acc[i], ah[i], bh);
                int r = wm * 64 + i * 16 + (lane & 15);
                LDSM4(al[i][0], al[i][1], al[i][2], al[i][3],
                      cs + GOFF_AL + r * PRB + kc * 32 + (lane >> 4) * 16);
                int gi = kc * 12 + i;
                if (pf && gi < 24) docp(gi, Ah, Al, Bh, Bl, k0n, ps, t);
            }
#pragma unroll
            for (int i = 0; i < 4; i++) {
                mma_g8(acc[i], al[i], bh);
                int r = wn * 64 + i * 16 + (lane >> 4) * 8 + (lane & 7);
                uint32_t a = cs + GOFF_BL + r * PRB + kc * 32 + ((lane >> 3) & 1) * 16;
                LDSM4(bl[2*i][0], bl[2*i][1], bl[2*i+1][0], bl[2*i+1][1], a);
                int gi = kc * 12 + 4 + i;
                if (pf && gi < 24) docp(gi, Ah, Al, Bh, Bl, k0n, ps, t);
            }
#pragma unroll
            for (int i = 0; i < 4; i++) {
                mma_g8(acc[i], ah[i], bl);
                int gi = kc * 12 + 8 + i;
                if (pf && gi < 24) docp(gi, Ah, Al, Bh, Bl, k0n, ps, t);
            }
        }
        CPC();
    }
}

__global__ __launch_bounds__(256, 1) void qkv_gemm_k()
{
    extern __shared__ char smg[];
    uint32_t sb = scvta(smg);
    const int m0 = blockIdx.y * 128;
    const int n0 = blockIdx.x * 256;

    float acc[4][8][4];
    gemm_main(gx_h + (size_t)m0 * 1024, gx_l + (size_t)m0 * 1024,
              gwq_h + (size_t)n0 * 1024, gwq_l + (size_t)n0 * 1024, sb, acc);

    const int t = threadIdx.x;
    const int lane = t & 31, wid = t >> 5;
    const int wm = wid >> 2, wn = wid & 3;
    const int g = lane >> 2, tq = lane & 3;

    const int which = n0 >> 10;
    __nv_bfloat16* dh = (which == 0) ? gq_h : (which == 1) ? gk_h : gv_h;
    __nv_bfloat16* dl = (which == 0) ? gq_l : (which == 1) ? gk_l : gv_l;
    const int h = ((n0 + wn * 64) >> 6) & (NH - 1);

#pragma unroll
    for (int i = 0; i < 4; i++) {
        int m = m0 + wm * 64 + i * 16 + g;
        int b = m >> 11, s = m & (S_ - 1);
#pragma unroll
        for (int j = 0; j < 8; j++) {
            int hd = j * 8 + 2 * tq;
            size_t idx = (((size_t)(b * NH + h) * S_ + s) * HD_ + hd);
            uint32_t hw, lw;
            split2(acc[i][j][0], acc[i][j][1], hw, lw);
            *(uint32_t*)(dh + idx) = hw;
            *(uint32_t*)(dl + idx) = lw;
            split2(acc[i][j][2], acc[i][j][3], hw, lw);
            *(uint32_t*)(dh + idx + 8 * HD_) = hw;
            *(uint32_t*)(dl + idx + 8 * HD_) = lw;
        }
    }
}

// ===========================================================================
// OUT GEMM: fp16 2-pass (A=ctx hi/lo, B=W_out hi). 3 tiles, 2 passes.
// ===========================================================================
#define H_A       (128 * PRB)
#define H_B       (256 * PRB)
#define HOFF_AL   H_A
#define HOFF_BH   (2 * H_A)
#define HSTAGE_B  (2 * H_A + H_B)
#define OUT_SMEM  (2 * HSTAGE_B)

__device__ __forceinline__ void gstage_h(const __half* Ah, const __half* Al,
                                         const __half* Bh, int k0, uint32_t sb, int t)
{
#pragma unroll
    for (int it = 0; it < 4; it++) {
        int idx = t + it * 256;
        int row = idx >> 3, c = idx & 7;
        uint32_t d = sb + row * PRB + c * 16;
        CPA16(d,           Ah + (size_t)row * 1024 + k0 + c * 8);
        CPA16(d + HOFF_AL, Al + (size_t)row * 1024 + k0 + c * 8);
    }
#pragma unroll
    for (int it = 0; it < 8; it++) {
        int idx = t + it * 256;
        int row = idx >> 3, c = idx & 7;
        CPA16(sb + HOFF_BH + row * PRB + c * 16, Bh + (size_t)row * 1024 + k0 + c * 8);
    }
}

__device__ __forceinline__ void docp_h(int j, const __half* Ah, const __half* Al,
                                       const __half* Bh, int k0, uint32_t sb, int t)
{
    if (j < 8) {
        int it = j & 3;
        int idx = t + it * 256;
        int row = idx >> 3, c = idx & 7;
        uint32_t d = sb + row * PRB + c * 16;
        if (j < 4) CPA16(d,           Ah + (size_t)row * 1024 + k0 + c * 8);
        else       CPA16(d + HOFF_AL, Al + (size_t)row * 1024 + k0 + c * 8);
    } else {
        int it = j - 8;
        int idx = t + it * 256;
        int row = idx >> 3, c = idx & 7;
        CPA16(sb + HOFF_BH + row * PRB + c * 16, Bh + (size_t)row * 1024 + k0 + c * 8);
    }
}

__device__ __forceinline__ void gemm_main_h(const __half* Ah, const __half* Al,
                                            const __half* Bh, uint32_t sb,
                                            float acc[4][8][4])
{
    const int t = threadIdx.x;
    const int lane = t & 31, wid = t >> 5;
    const int wm = wid >> 2, wn = wid & 3;

#pragma unroll
    for (int i = 0; i < 4; i++)
#pragma unroll
        for (int j = 0; j < 8; j++)
#pragma unroll
            for (int c = 0; c < 4; c++) acc[i][j][c] = 0.f;

    gstage_h(Ah, Al, Bh, 0, sb, t);
    CPC();

    for (int ks = 0; ks < 16; ks++) {
        CPW(0);
        __syncthreads();
        const uint32_t cs = sb + (ks & 1) * HSTAGE_B;
        const uint32_t ps = sb + ((ks + 1) & 1) * HSTAGE_B;
        const int k0n = (ks + 1) * 64;
        const bool pf = (ks < 15);

#pragma unroll
        for (int kc = 0; kc < 4; kc++) {
            uint32_t ah[4][4], al[4][4], bh[8][2];
#pragma unroll
            for (int jp = 0; jp < 4; jp++) {
                int r = wn * 64 + jp * 16 + (lane >> 4) * 8 + (lane & 7);
                uint32_t a = cs + HOFF_BH + r * PRB + kc * 32 + ((lane >> 3) & 1) * 16;
                LDSM4(bh[2*jp][0], bh[2*jp][1], bh[2*jp+1][0], bh[2*jp+1][1], a);
            }
#pragma unroll
            for (int i = 0; i < 4; i++) {
                int r = wm * 64 + i * 16 + (lane & 15);
                LDSM4(ah[i][0], ah[i][1], ah[i][2], ah[i][3],
                      cs + r * PRB + kc * 32 + (lane >> 4) * 16);
            }
#pragma unroll
            for (int i = 0; i < 4; i++) {
                mma_g8h(acc[i], ah[i], bh);
                int r = wm * 64 + i * 16 + (lane & 15);
                LDSM4(al[i][0], al[i][1], al[i][2], al[i][3],
                      cs + HOFF_AL + r * PRB + kc * 32 + (lane >> 4) * 16);
                int gi = kc * 8 + i;
                if (pf && gi < 16) docp_h(gi, Ah, Al, Bh, k0n, ps, t);
            }
#pragma unroll
            for (int i = 0; i < 4; i++) {
                mma_g8h(acc[i], al[i], bh);
                int gi = kc * 8 + 4 + i;
                if (pf && gi < 16) docp_h(gi, Ah, Al, Bh, k0n, ps, t);
            }
        }
        CPC();
    }
}

__global__ __launch_bounds__(256, 1) void out_gemm_k(const float* __restrict__ bias,
                                                     float* __restrict__ out)
{
    extern __shared__ char smg[];
    uint32_t sb = scvta(smg);
    const int m0 = blockIdx.y * 128;
    const int n0 = blockIdx.x * 256;

    float acc[4][8][4];
    gemm_main_h(gc_h + (size_t)m0 * 1024, gc_l + (size_t)m0 * 1024,
                gwoh + (size_t)n0 * 1024, sb, acc);

    const int t = threadIdx.x;
    const int lane = t & 31, wid = t >> 5;
    const int wm = wid >> 2, wn = wid & 3;
    const int g = lane >> 2, tq = lane & 3;

#pragma unroll
    for (int i = 0; i < 4; i++) {
        int m = m0 + wm * 64 + i * 16 + g;
#pragma unroll
        for (int j = 0; j < 8; j++) {
            int nn = n0 + wn * 64 + j * 8 + 2 * tq;
            float2 bb = *(const float2*)(bias + nn);
            float* p = out + (size_t)m * DOUT + nn;
            *(float2*)p              = make_float2(acc[i][j][0] + bb.x, acc[i][j][1] + bb.y);
            *(float2*)(p + 8 * DOUT) = make_float2(acc[i][j][2] + bb.x, acc[i][j][3] + bb.y);
        }
    }
}

// ===========================================================================
// Attention (R11 structure; ctx epilogue now fp16 hi/lo).
// ===========================================================================
#define ATQ      128
#define ANT      128
#define APB      144
#define ATILE_B  (64 * APB)
#define ASTAGE_B (4 * ATILE_B)
#define AQ_B     (128 * APB)
#define ATTN_SMEM (2 * ASTAGE_B)

__device__ __forceinline__ void aload_tile(const __nv_bfloat16* src, uint32_t dst, int t)
{
#pragma unroll
    for (int it = 0; it < 4; it++) {
        int idx = t + it * ANT;
        int row = idx >> 3, c = idx & 7;
        CPA16(dst + row * APB + c * 16, src + (size_t)row * HD_ + c * 8);
    }
}
__device__ __forceinline__ void aload_q(const __nv_bfloat16* src, uint32_t dst, int t)
{
#pragma unroll
    for (int it = 0; it < 8; it++) {
        int idx = t + it * ANT;
        int row = idx >> 3, c = idx & 7;
        CPA16(dst + row * APB + c * 16, src + (size_t)row * HD_ + c * 8);
    }
}

__device__ __forceinline__ void docpa(int j, const __nv_bfloat16* kh, const __nv_bfloat16* kl,
                                      const __nv_bfloat16* vh, const __nv_bfloat16* vl,
                                      uint32_t ns, int t)
{
    int tile = j >> 2;
    int idx  = t + (j & 3) * ANT;
    int row = idx >> 3, c = idx & 7;
    const __nv_bfloat16* src = (tile == 0) ? kh : (tile == 1) ? kl : (tile == 2) ? vh : vl;
    CPA16(ns + tile * ATILE_B + row * APB + c * 16, src + (size_t)row * HD_ + c * 8);
}

__device__ __forceinline__ void attn_block(
    uint32_t ks, int kc, int row0,
    const uint32_t (*qh)[4], const uint32_t (*ql)[4],
    float* m_, float* l_, float (*oacc)[4],
    bool dopf,
    const __nv_bfloat16* kh, const __nv_bfloat16* kl,
    const __nv_bfloat16* vh, const __nv_bfloat16* vl,
    uint32_t ns, int t, int lane, int g, int tq)
{
    float sacc[8][4];
#pragma unroll
    for (int j = 0; j < 8; j++)
#pragma unroll
        for (int cc = 0; cc < 4; cc++) sacc[j][cc] = 0.f;

#pragma unroll
    for (int kc2 = 0; kc2 < 4; kc2++) {
#pragma unroll
        for (int jp = 0; jp < 4; jp++) {
            int r = jp * 16 + (lane >> 4) * 8 + (lane & 7);
            uint32_t a = ks + r * APB + kc2 * 32 + ((lane >> 3) & 1) * 16;
            uint32_t bh0[2], bh1[2], bl0[2], bl1[2];
            LDSM4(bh0[0], bh0[1], bh1[0], bh1[1], a);
            LDSM4(bl0[0], bl0[1], bl1[0], bl1[1], a + ATILE_B);
            mma_bf16(sacc[2*jp],   qh[kc2], bh0);
            mma_bf16(sacc[2*jp],   ql[kc2], bh0);
            mma_bf16(sacc[2*jp],   qh[kc2], bl0);
            mma_bf16(sacc[2*jp+1], qh[kc2], bh1);
            mma_bf16(sacc[2*jp+1], ql[kc2], bh1);
            mma_bf16(sacc[2*jp+1], qh[kc2], bl1);
            int gi = kc2 * 4 + jp;
            if (dopf) docpa(gi, kh, kl, vh, vl, ns, t);
        }
    }

#pragma unroll
    for (int half = 0; half < 2; half++) {
        int row = row0 + 8 * half;
        float mx = -INFINITY;
#pragma unroll
        for (int j = 0; j < 8; j++) {
            int col = kc + 8 * j + 2 * tq;
            float v0 = sacc[j][2 * half];
            float v1 = sacc[j][2 * half + 1];
            int d0 = row - col;     d0 = d0 < 0 ? -d0 : d0;
            int d1 = row - col - 1; d1 = d1 < 0 ? -d1 : d1;
            v0 = (d0 <= WIN) ? v0 * SCALE : -INFINITY;
            v1 = (d1 <= WIN) ? v1 * SCALE : -INFINITY;
            sacc[j][2 * half]     = v0;
            sacc[j][2 * half + 1] = v1;
            mx = fmaxf(mx, fmaxf(v0, v1));
        }
        mx = fmaxf(mx, __shfl_xor_sync(0xffffffffu, mx, 1, 4));
        mx = fmaxf(mx, __shfl_xor_sync(0xffffffffu, mx, 2, 4));

        float mn    = fmaxf(m_[half], mx);
        float msafe = (mn == -INFINITY) ? 0.f : mn;
        float alpha = __expf(m_[half] - msafe);
        m_[half] = mn;

        float rs = 0.f;
#pragma unroll
        for (int j = 0; j < 8; j++) {
            float p0 = __expf(sacc[j][2 * half]     - msafe);
            float p1 = __expf(sacc[j][2 * half + 1] - msafe);
            sacc[j][2 * half]     = p0;
            sacc[j][2 * half + 1] = p1;
            rs += p0 + p1;
        }
        rs += __shfl_xor_sync(0xffffffffu, rs, 1, 4);
        rs += __shfl_xor_sync(0xffffffffu, rs, 2, 4);
        l_[half] = l_[half] * alpha + rs;
#pragma unroll
        for (int j = 0; j < 8; j++) {
            oacc[j][2 * half]     *= alpha;
            oacc[j][2 * half + 1] *= alpha;
        }
    }

#pragma unroll
    for (int kp = 0; kp < 4; kp++) {
        uint32_t ph[4], pl[4];
        split2(sacc[2*kp][0],   sacc[2*kp][1],   ph[0], pl[0]);
        split2(sacc[2*kp][2],   sacc[2*kp][3],   ph[1], pl[1]);
        split2(sacc[2*kp+1][0], sacc[2*kp+1][1], ph[2], pl[2]);
        split2(sacc[2*kp+1][2], sacc[2*kp+1][3], ph[3], pl[3]);

#pragma unroll
        for (int jp = 0; jp < 4; jp++) {
            int keyrow = kp * 16 + ((lane >> 3) & 1) * 8 + (lane & 7);
            uint32_t a = ks + 2 * ATILE_B + keyrow * APB + (2 * jp + (lane >> 4)) * 16;
            uint32_t vh0[2], vh1[2], vl0[2], vl1[2];
            LDSM4T(vh0[0], vh0[1], vh1[0], vh1[1], a);
            LDSM4T(vl0[0], vl0[1], vl1[0], vl1[1], a + ATILE_B);
            mma_bf16(oacc[2*jp],   ph, vh0);
            mma_bf16(oacc[2*jp],   pl, vh0);
            mma_bf16(oacc[2*jp],   ph, vl0);
            mma_bf16(oacc[2*jp+1], ph, vh1);
            mma_bf16(oacc[2*jp+1], pl, vh1);
            mma_bf16(oacc[2*jp+1], ph, vl1);
        }
    }
}

__global__ __launch_bounds__(ANT, 2) void attn_k()
{
    extern __shared__ char sma[];
    uint32_t sb = scvta(sma);

    const int t    = threadIdx.x;
    const int lane = t & 31;
    const int w    = t >> 5;
    const int g    = lane >> 2;
    const int tq   = lane & 3;

    const int q0 = blockIdx.x * ATQ;
    const int h  = blockIdx.y;
    const int b  = blockIdx.z;
    const size_t hb = (size_t)(b * NH + h) * S_ * HD_;

    int kc0 = q0 - WIN; if (kc0 < 0) kc0 = 0;
    int kce = q0 + ATQ + WIN; if (kce > S_) kce = S_;
    const int nch = (kce - kc0) >> 6;

    aload_q(gq_h + hb + (size_t)q0 * HD_, sb,        t);
    aload_q(gq_l + hb + (size_t)q0 * HD_, sb + AQ_B, t);
    CPC();
    CPW(0);
    __syncthreads();

    uint32_t qh[2][4][4], ql[2][4][4];
#pragma unroll
    for (int blk = 0; blk < 2; blk++) {
        int r = 32 * w + 16 * blk + (lane & 15);
#pragma unroll
        for (int kc = 0; kc < 4; kc++) {
            uint32_t a = sb + r * APB + kc * 32 + (lane >> 4) * 16;
            LDSM4(qh[blk][kc][0], qh[blk][kc][1], qh[blk][kc][2], qh[blk][kc][3], a);
            LDSM4(ql[blk][kc][0], ql[blk][kc][1], ql[blk][kc][2], ql[blk][kc][3], a + AQ_B);
        }
    }
    __syncthreads();

    {
        size_t off = hb + (size_t)kc0 * HD_;
        aload_tile(gk_h + off, sb,               t);
        aload_tile(gk_l + off, sb + ATILE_B,     t);
        aload_tile(gv_h + off, sb + 2 * ATILE_B, t);
        aload_tile(gv_l + off, sb + 3 * ATILE_B, t);
    }
    CPC();

    float oacc[2][8][4];
#pragma unroll
    for (int blk = 0; blk < 2; blk++)
#pragma unroll
        for (int j = 0; j < 8; j++)
#pragma unroll
            for (int c = 0; c < 4; c++) oacc[blk][j][c] = 0.f;
    float m_[2][2] = {{-INFINITY, -INFINITY}, {-INFINITY, -INFINITY}};
    float l_[2][2] = {{0.f, 0.f}, {0.f, 0.f}};

    const int qlo0 = q0 + 32 * w;
    const int qlo1 = qlo0 + 16;

    for (int c = 0; c < nch; c++) {
        const int kc = kc0 + c * 64;
        CPW(0);
        __syncthreads();
        const uint32_t ks = sb + (c & 1) * ASTAGE_B;
        const uint32_t ns = sb + ((c + 1) & 1) * ASTAGE_B;
        const bool pf = (c + 1 < nch);
        const size_t noff = hb + (size_t)(kc + 64) * HD_;
        const __nv_bfloat16 *kh = gk_h + noff, *kl = gk_l + noff;
        const __nv_bfloat16 *vh = gv_h + noff, *vl = gv_l + noff;

        bool a0 = (kc + 64 > qlo0 - WIN) && (kc <= qlo0 + 15 + WIN);
        bool a1 = (kc + 64 > qlo1 - WIN) && (kc <= qlo1 + 15 + WIN);

        if (pf && !a0) {
#pragma unroll
            for (int j = 0; j < 16; j++) docpa(j, kh, kl, vh, vl, ns, t);
        }
        if (a0)
            attn_block(ks, kc, qlo0 + g, qh[0], ql[0], m_[0], l_[0], oacc[0],
                       pf, kh, kl, vh, vl, ns, t, lane, g, tq);
        if (a1)
            attn_block(ks, kc, qlo1 + g, qh[1], ql[1], m_[1], l_[1], oacc[1],
                       false, kh, kl, vh, vl, ns, t, lane, g, tq);
        CPC();
    }

#pragma unroll
    for (int blk = 0; blk < 2; blk++) {
        int row0 = q0 + 32 * w + 16 * blk + g;
        float rl0 = 1.f / l_[blk][0];
        float rl1 = 1.f / l_[blk][1];
        size_t c0 = ((size_t)b * S_ + row0) * DOUT + h * HD_;
        size_t c1 = c0 + 8 * DOUT;
#pragma unroll
        for (int j = 0; j < 8; j++) {
            int hd = 8 * j + 2 * tq;
            uint32_t hw, lw;
            split2h(oacc[blk][j][0] * rl0, oacc[blk][j][1] * rl0, hw, lw);
            *(uint32_t*)(gc_h + c0 + hd) = hw;
            *(uint32_t*)(gc_l + c0 + hd) = lw;
            split2h(oacc[blk][j][2] * rl1, oacc[blk][j][3] * rl1, hw, lw);
            *(uint32_t*)(gc_h + c1 + hd) = hw;
            *(uint32_t*)(gc_l + c1 + hd) = lw;
        }
    }
}

// ===========================================================================
extern "C" void kernel_launch(void* const* d_in, const int* in_sizes, int n_in,
                              void* d_out, int out_size)
{
    const float* x    = (const float*)d_in[0];
    const float* wqkv = (const float*)d_in[1];
    const float* wout = (const float*)d_in[2];
    const float* bout = (const float*)d_in[3];
    float* out = (float*)d_out;

    cudaFuncSetAttribute(qkv_gemm_k, cudaFuncAttributeMaxDynamicSharedMemorySize, GEMM_SMEM);
    cudaFuncSetAttribute(out_gemm_k, cudaFuncAttributeMaxDynamicSharedMemorySize, OUT_SMEM);
    cudaFuncSetAttribute(attn_k, cudaFuncAttributeMaxDynamicSharedMemorySize, ATTN_SMEM);

    split_all_kernel<<<N8_ALL / 256, 256>>>((const float4*)x, (const float4*)wqkv,
                                            (const float4*)wout);

    qkv_gemm_k<<<dim3(3 * DOUT / 256, (B_ * S_) / 128), 256, GEMM_SMEM>>>();
    attn_k<<<dim3(S_ / ATQ, NH, B_), ANT, ATTN_SMEM>>>();
    out_gemm_k<<<dim3(DOUT / 256, (B_ * S_) / 128), 256, OUT_SMEM>>>(bout, out);
}